// round 1
// baseline (speedup 1.0000x reference)
#include <cuda_runtime.h>
#include <cuda_bf16.h>
#include <cstdint>

// Problem constants
#define BATCH 4
#define SEQ 4096
#define DMODEL 1024
#define NHEAD 16
#define HDIM 64
#define MROWS (BATCH * SEQ)        // 16384
#define NROWS_SM (MROWS * NHEAD)   // 262144 softmax rows
#define BH (BATCH * NHEAD)         // 64

// Scratch (device globals; no cudaMalloc allowed)
__device__ float g_Q[MROWS * DMODEL];
__device__ float g_K[MROWS * DMODEL];
__device__ float g_V[MROWS * DMODEL];
__device__ float g_AO[MROWS * DMODEL];
__device__ float g_KVp[8 * BH * HDIM * HDIM];   // split-S partials (deterministic)
__device__ float g_KV[BH * HDIM * HDIM];

// ---------------------------------------------------------------------------
// TF32 helpers
// ---------------------------------------------------------------------------
__device__ __forceinline__ float to_tf32(float x) {
    uint32_t u;
    asm("cvt.rna.tf32.f32 %0, %1;" : "=r"(u) : "f"(x));
    return __uint_as_float(u);
}

__device__ __forceinline__ void mma_tf32(float c[4], const uint32_t a[4], const uint32_t b[2]) {
    asm volatile(
        "mma.sync.aligned.m16n8k8.row.col.f32.tf32.tf32.f32 "
        "{%0,%1,%2,%3}, {%4,%5,%6,%7}, {%8,%9}, {%0,%1,%2,%3};\n"
        : "+f"(c[0]), "+f"(c[1]), "+f"(c[2]), "+f"(c[3])
        : "r"(a[0]), "r"(a[1]), "r"(a[2]), "r"(a[3]), "r"(b[0]), "r"(b[1]));
}

// ---------------------------------------------------------------------------
// GEMM: C[M,N] = A[M,K] @ B[K,N] + bias[N]   (fp32 in, tf32 mma, fp32 accum)
// BM=128 BN=128 BK=32, 256 threads, warp grid 2x4 (64x32 per warp)
// ---------------------------------------------------------------------------
#define BM 128
#define BN 128
#define BK 32
#define AS_STRIDE (BK + 4)     // 36: a-frag loads conflict-free
#define BS_STRIDE (BN + 8)     // 136: b-frag loads conflict-free

__global__ void __launch_bounds__(256)
gemm_tf32(const float* __restrict__ A, const float* __restrict__ B,
          const float* __restrict__ bias, float* __restrict__ C,
          int M, int N, int K) {
    __shared__ float As[BM][AS_STRIDE];
    __shared__ float Bs[BK][BS_STRIDE];

    const int tid  = threadIdx.x;
    const int warp = tid >> 5;
    const int lane = tid & 31;
    const int g  = lane >> 2;   // group id 0..7
    const int tg = lane & 3;    // thread-in-group 0..3
    const int wm = (warp >> 2) * 64;   // warp m offset: 0 / 64
    const int wn = (warp & 3) * 32;    // warp n offset: 0/32/64/96
    const int bm = blockIdx.y * BM;
    const int bn = blockIdx.x * BN;

    float acc[4][4][4] = {};

    for (int kt = 0; kt < K; kt += BK) {
        // load A tile 128x32 (float4, convert to tf32 on store)
        #pragma unroll
        for (int i = 0; i < 4; i++) {
            int f = tid + i * 256;              // 0..1023
            int r = f >> 3;                     // 0..127
            int c = (f & 7) * 4;                // 0..28
            float4 v = *(const float4*)&A[(size_t)(bm + r) * K + kt + c];
            As[r][c + 0] = to_tf32(v.x);
            As[r][c + 1] = to_tf32(v.y);
            As[r][c + 2] = to_tf32(v.z);
            As[r][c + 3] = to_tf32(v.w);
        }
        // load B tile 32x128
        #pragma unroll
        for (int i = 0; i < 4; i++) {
            int f = tid + i * 256;
            int r = f >> 5;                     // 0..31
            int c = (f & 31) * 4;               // 0..124
            float4 v = *(const float4*)&B[(size_t)(kt + r) * N + bn + c];
            Bs[r][c + 0] = to_tf32(v.x);
            Bs[r][c + 1] = to_tf32(v.y);
            Bs[r][c + 2] = to_tf32(v.z);
            Bs[r][c + 3] = to_tf32(v.w);
        }
        __syncthreads();

        #pragma unroll
        for (int k0 = 0; k0 < BK; k0 += 8) {
            uint32_t af[4][4];
            uint32_t bf[4][2];
            #pragma unroll
            for (int mi = 0; mi < 4; mi++) {
                int m0 = wm + mi * 16;
                af[mi][0] = __float_as_uint(As[m0 + g    ][k0 + tg    ]);
                af[mi][1] = __float_as_uint(As[m0 + g + 8][k0 + tg    ]);
                af[mi][2] = __float_as_uint(As[m0 + g    ][k0 + tg + 4]);
                af[mi][3] = __float_as_uint(As[m0 + g + 8][k0 + tg + 4]);
            }
            #pragma unroll
            for (int ni = 0; ni < 4; ni++) {
                int n0 = wn + ni * 8;
                bf[ni][0] = __float_as_uint(Bs[k0 + tg    ][n0 + g]);
                bf[ni][1] = __float_as_uint(Bs[k0 + tg + 4][n0 + g]);
            }
            #pragma unroll
            for (int mi = 0; mi < 4; mi++)
                #pragma unroll
                for (int ni = 0; ni < 4; ni++)
                    mma_tf32(acc[mi][ni], af[mi], bf[ni]);
        }
        __syncthreads();
    }

    // epilogue + bias
    #pragma unroll
    for (int mi = 0; mi < 4; mi++) {
        int row = bm + wm + mi * 16 + g;
        #pragma unroll
        for (int ni = 0; ni < 4; ni++) {
            int col = bn + wn + ni * 8 + tg * 2;
            float b0 = bias ? bias[col]     : 0.f;
            float b1 = bias ? bias[col + 1] : 0.f;
            C[(size_t)row * N + col]           = acc[mi][ni][0] + b0;
            C[(size_t)row * N + col + 1]       = acc[mi][ni][1] + b1;
            C[(size_t)(row + 8) * N + col]     = acc[mi][ni][2] + b0;
            C[(size_t)(row + 8) * N + col + 1] = acc[mi][ni][3] + b1;
        }
    }
}

// ---------------------------------------------------------------------------
// Row softmax over 64 contiguous elements. One warp per row, 2 elems/lane.
// ---------------------------------------------------------------------------
__global__ void __launch_bounds__(256)
softmax64(float* __restrict__ X, int nrows) {
    int wrow = (blockIdx.x * blockDim.x + threadIdx.x) >> 5;
    int lane = threadIdx.x & 31;
    if (wrow >= nrows) return;
    float* row = X + (size_t)wrow * 64;
    float v0 = row[lane], v1 = row[lane + 32];
    float m = fmaxf(v0, v1);
    #pragma unroll
    for (int o = 16; o; o >>= 1) m = fmaxf(m, __shfl_xor_sync(0xffffffffu, m, o));
    float e0 = __expf(v0 - m), e1 = __expf(v1 - m);
    float s = e0 + e1;
    #pragma unroll
    for (int o = 16; o; o >>= 1) s += __shfl_xor_sync(0xffffffffu, s, o);
    float inv = 1.f / s;
    row[lane]      = e0 * inv;
    row[lane + 32] = e1 * inv;
}

// ---------------------------------------------------------------------------
// KV partials: KVp[chunk,bh,d,e] = sum_{s in chunk} K[b,s,h,d] * V[b,s,h,e]
// grid (8 chunks, 64 bh), 256 threads, each thread owns a 4x4 sub-tile.
// ---------------------------------------------------------------------------
__global__ void __launch_bounds__(256)
kv_partial(const float* __restrict__ Ksm, const float* __restrict__ V,
           float* __restrict__ KVp) {
    __shared__ float Ks[32][64];
    __shared__ float Vs[32][64];
    const int chunk = blockIdx.x;
    const int bh = blockIdx.y;
    const int b = bh >> 4, h = bh & 15;
    const int tid = threadIdx.x;
    const int td = (tid >> 4) * 4;
    const int te = (tid & 15) * 4;
    float acc[4][4] = {};

    const size_t rowbase = ((size_t)b * SEQ + chunk * 512) * DMODEL + h * 64;

    for (int sub = 0; sub < 16; sub++) {
        #pragma unroll
        for (int i = 0; i < 2; i++) {
            int f = tid + i * 256;              // 0..511
            int r = f >> 4;                     // 0..31
            int c = (f & 15) * 4;               // 0..60
            size_t ga = rowbase + (size_t)(sub * 32 + r) * DMODEL + c;
            *(float4*)&Ks[r][c] = *(const float4*)&Ksm[ga];
            *(float4*)&Vs[r][c] = *(const float4*)&V[ga];
        }
        __syncthreads();
        #pragma unroll
        for (int s = 0; s < 32; s++) {
            float4 k4 = *(float4*)&Ks[s][td];
            float4 v4 = *(float4*)&Vs[s][te];
            float kk[4] = {k4.x, k4.y, k4.z, k4.w};
            float vv[4] = {v4.x, v4.y, v4.z, v4.w};
            #pragma unroll
            for (int i = 0; i < 4; i++)
                #pragma unroll
                for (int j = 0; j < 4; j++)
                    acc[i][j] += kk[i] * vv[j];
        }
        __syncthreads();
    }

    float* out = KVp + ((size_t)chunk * BH + bh) * (HDIM * HDIM);
    #pragma unroll
    for (int i = 0; i < 4; i++)
        #pragma unroll
        for (int j = 0; j < 4; j++)
            out[(td + i) * 64 + te + j] = acc[i][j];
}

__global__ void __launch_bounds__(256)
kv_reduce(const float* __restrict__ KVp, float* __restrict__ KV) {
    int idx = blockIdx.x * blockDim.x + threadIdx.x;
    if (idx >= BH * HDIM * HDIM) return;
    float s = 0.f;
    #pragma unroll
    for (int c = 0; c < 8; c++)
        s += KVp[(size_t)c * BH * HDIM * HDIM + idx];
    KV[idx] = s;
}

// ---------------------------------------------------------------------------
// Apply: AO[b,s,h,e] = sum_d Q[b,s,h,d] * KV[bh,d,e]
// grid (16 s-chunks, 64 bh), 256 threads; KV tile resident in smem.
// ---------------------------------------------------------------------------
__global__ void __launch_bounds__(256)
apply_kv(const float* __restrict__ Qsm, const float* __restrict__ KV,
         float* __restrict__ AO) {
    __shared__ float KVs[64][64];
    const int chunk = blockIdx.x;
    const int bh = blockIdx.y;
    const int b = bh >> 4, h = bh & 15;
    const int tid = threadIdx.x, warp = tid >> 5, lane = tid & 31;

    const float* kvsrc = KV + (size_t)bh * (HDIM * HDIM);
    #pragma unroll
    for (int i = 0; i < 4; i++) {
        int f = tid + i * 256;                  // 0..1023 float4s
        *(float4*)(&KVs[0][0] + f * 4) = *(const float4*)(kvsrc + f * 4);
    }
    __syncthreads();

    for (int r = 0; r < 32; r++) {
        int s = chunk * 256 + warp * 32 + r;
        size_t base = ((size_t)b * SEQ + s) * DMODEL + h * 64;
        float q0 = Qsm[base + lane];
        float q1 = Qsm[base + lane + 32];
        float o0 = 0.f, o1 = 0.f;
        #pragma unroll
        for (int d = 0; d < 64; d++) {
            float qd = __shfl_sync(0xffffffffu, (d < 32 ? q0 : q1), d & 31);
            o0 += qd * KVs[d][lane];
            o1 += qd * KVs[d][lane + 32];
        }
        AO[base + lane]      = o0;
        AO[base + lane + 32] = o1;
    }
}

// ---------------------------------------------------------------------------
// Launch
// ---------------------------------------------------------------------------
extern "C" void kernel_launch(void* const* d_in, const int* in_sizes, int n_in,
                              void* d_out, int out_size) {
    const float* x  = (const float*)d_in[0];
    const float* Wq = (const float*)d_in[1];
    const float* bq = (const float*)d_in[2];
    const float* Wk = (const float*)d_in[3];
    const float* bk = (const float*)d_in[4];
    const float* Wv = (const float*)d_in[5];
    const float* bv = (const float*)d_in[6];
    const float* Wo = (const float*)d_in[7];
    const float* bo = (const float*)d_in[8];
    float* out = (float*)d_out;

    float *Q, *K, *V, *AO, *KVp, *KV;
    cudaGetSymbolAddress((void**)&Q,   g_Q);
    cudaGetSymbolAddress((void**)&K,   g_K);
    cudaGetSymbolAddress((void**)&V,   g_V);
    cudaGetSymbolAddress((void**)&AO,  g_AO);
    cudaGetSymbolAddress((void**)&KVp, g_KVp);
    cudaGetSymbolAddress((void**)&KV,  g_KV);

    dim3 ggrid(DMODEL / BN, MROWS / BM);   // (8, 128)

    gemm_tf32<<<ggrid, 256>>>(x, Wq, bq, Q, MROWS, DMODEL, DMODEL);
    gemm_tf32<<<ggrid, 256>>>(x, Wk, bk, K, MROWS, DMODEL, DMODEL);
    gemm_tf32<<<ggrid, 256>>>(x, Wv, bv, V, MROWS, DMODEL, DMODEL);

    softmax64<<<NROWS_SM / 8, 256>>>(Q, NROWS_SM);
    softmax64<<<NROWS_SM / 8, 256>>>(K, NROWS_SM);

    kv_partial<<<dim3(8, BH), 256>>>(K, V, KVp);
    kv_reduce<<<(BH * HDIM * HDIM + 255) / 256, 256>>>(KVp, KV);
    apply_kv<<<dim3(16, BH), 256>>>(Q, KV, AO);

    gemm_tf32<<<ggrid, 256>>>(AO, Wo, bo, out, MROWS, DMODEL, DMODEL);
}

// round 2
// speedup vs baseline: 1.1336x; 1.1336x over previous
#include <cuda_runtime.h>
#include <cuda_bf16.h>
#include <cstdint>

// Problem constants
#define BATCH 4
#define SEQ 4096
#define DMODEL 1024
#define NHEAD 16
#define HDIM 64
#define MROWS (BATCH * SEQ)        // 16384
#define BH (BATCH * NHEAD)         // 64

// Scratch (device globals; no cudaMalloc allowed)
__device__ float g_Q[MROWS * DMODEL];
__device__ float g_K[MROWS * DMODEL];
__device__ float g_V[MROWS * DMODEL];
__device__ float g_AO[MROWS * DMODEL];
__device__ float g_KVp[8 * BH * HDIM * HDIM];   // split-S partials (deterministic)
__device__ float g_KV[BH * HDIM * HDIM];

// ---------------------------------------------------------------------------
// Helpers
// ---------------------------------------------------------------------------
__device__ __forceinline__ uint32_t f2tf(float x) {
    uint32_t u;
    asm("cvt.rna.tf32.f32 %0, %1;" : "=r"(u) : "f"(x));
    return u;
}

__device__ __forceinline__ void mma_tf32(float c[4], const uint32_t a[4], const uint32_t b[2]) {
    asm volatile(
        "mma.sync.aligned.m16n8k8.row.col.f32.tf32.tf32.f32 "
        "{%0,%1,%2,%3}, {%4,%5,%6,%7}, {%8,%9}, {%0,%1,%2,%3};\n"
        : "+f"(c[0]), "+f"(c[1]), "+f"(c[2]), "+f"(c[3])
        : "r"(a[0]), "r"(a[1]), "r"(a[2]), "r"(a[3]), "r"(b[0]), "r"(b[1]));
}

__device__ __forceinline__ void cp_async16(void* smem, const void* gmem) {
    uint32_t s = (uint32_t)__cvta_generic_to_shared(smem);
    asm volatile("cp.async.cg.shared.global [%0], [%1], 16;\n" :: "r"(s), "l"(gmem));
}
__device__ __forceinline__ void cp_commit() { asm volatile("cp.async.commit_group;\n"); }
template<int N>
__device__ __forceinline__ void cp_wait() { asm volatile("cp.async.wait_group %0;\n" :: "n"(N)); }

// ---------------------------------------------------------------------------
// Pipelined TF32 GEMM: C[M,N] = A[M,K] @ B[K,N] + bias[N], optional fused
// per-64-col-group softmax (head_dim softmax for Q/K).
// BM=128 BN=128 BK=32, 3-stage cp.async pipeline, 256 threads.
// ---------------------------------------------------------------------------
#define BM 128
#define BN 128
#define BK 32
#define STAGES 3
#define AS_STRIDE (BK + 4)     // 36
#define BS_STRIDE (BN + 8)     // 136
#define TILE_STRIDE (BN + 4)   // 132, epilogue softmax staging

struct SmemPipe {
    float As[STAGES][BM][AS_STRIDE];
    float Bs[STAGES][BK][BS_STRIDE];
};

template<bool DO_SOFTMAX>
__global__ void __launch_bounds__(256, 2)
gemm_tf32(const float* __restrict__ A, const float* __restrict__ B,
          const float* __restrict__ bias, float* __restrict__ C,
          int M, int N, int K) {
    extern __shared__ char smem_raw[];
    SmemPipe& sp = *reinterpret_cast<SmemPipe*>(smem_raw);
    float (*tile)[TILE_STRIDE] = reinterpret_cast<float(*)[TILE_STRIDE]>(smem_raw);

    const int tid  = threadIdx.x;
    const int warp = tid >> 5;
    const int lane = tid & 31;
    const int g  = lane >> 2;
    const int tg = lane & 3;
    const int wm = (warp >> 2) * 64;
    const int wn = (warp & 3) * 32;
    const int bm = blockIdx.y * BM;
    const int bn = blockIdx.x * BN;

    const int T = K / BK;   // 32

    // stage loader
    auto load_stage = [&](int kt, int st) {
        #pragma unroll
        for (int i = 0; i < 4; i++) {
            int f = tid + i * 256;
            int r = f >> 3, c = (f & 7) * 4;
            cp_async16(&sp.As[st][r][c], &A[(size_t)(bm + r) * K + kt + c]);
        }
        #pragma unroll
        for (int i = 0; i < 4; i++) {
            int f = tid + i * 256;
            int r = f >> 5, c = (f & 31) * 4;
            cp_async16(&sp.Bs[st][r][c], &B[(size_t)(kt + r) * N + bn + c]);
        }
        cp_commit();
    };

    float acc[4][4][4] = {};

    load_stage(0, 0);
    load_stage(BK, 1);

    for (int t = 0; t < T; t++) {
        if (t > 0) __syncthreads();           // stage (t+2)%3 free for overwrite
        if (t + 2 < T) {
            load_stage((t + 2) * BK, (t + 2) % STAGES);
            cp_wait<2>();
        } else if (t + 1 < T) {
            cp_wait<1>();
        } else {
            cp_wait<0>();
        }
        __syncthreads();                       // stage t data visible

        const int st = t % STAGES;
        #pragma unroll
        for (int k0 = 0; k0 < BK; k0 += 8) {
            uint32_t af[4][4];
            uint32_t bf[4][2];
            #pragma unroll
            for (int mi = 0; mi < 4; mi++) {
                int m0 = wm + mi * 16;
                af[mi][0] = f2tf(sp.As[st][m0 + g    ][k0 + tg    ]);
                af[mi][1] = f2tf(sp.As[st][m0 + g + 8][k0 + tg    ]);
                af[mi][2] = f2tf(sp.As[st][m0 + g    ][k0 + tg + 4]);
                af[mi][3] = f2tf(sp.As[st][m0 + g + 8][k0 + tg + 4]);
            }
            #pragma unroll
            for (int ni = 0; ni < 4; ni++) {
                int n0 = wn + ni * 8;
                bf[ni][0] = f2tf(sp.Bs[st][k0 + tg    ][n0 + g]);
                bf[ni][1] = f2tf(sp.Bs[st][k0 + tg + 4][n0 + g]);
            }
            #pragma unroll
            for (int mi = 0; mi < 4; mi++)
                #pragma unroll
                for (int ni = 0; ni < 4; ni++)
                    mma_tf32(acc[mi][ni], af[mi], bf[ni]);
        }
    }

    if (!DO_SOFTMAX) {
        // direct epilogue
        #pragma unroll
        for (int mi = 0; mi < 4; mi++) {
            int row = bm + wm + mi * 16 + g;
            #pragma unroll
            for (int ni = 0; ni < 4; ni++) {
                int col = bn + wn + ni * 8 + tg * 2;
                float b0 = bias[col], b1 = bias[col + 1];
                C[(size_t)row * N + col]           = acc[mi][ni][0] + b0;
                C[(size_t)row * N + col + 1]       = acc[mi][ni][1] + b1;
                C[(size_t)(row + 8) * N + col]     = acc[mi][ni][2] + b0;
                C[(size_t)(row + 8) * N + col + 1] = acc[mi][ni][3] + b1;
            }
        }
    } else {
        // stage acc (+bias) into smem tile, then per-(row, 64-col-group) softmax
        __syncthreads();   // done with pipeline smem
        #pragma unroll
        for (int mi = 0; mi < 4; mi++) {
            int r = wm + mi * 16 + g;
            #pragma unroll
            for (int ni = 0; ni < 4; ni++) {
                int c = wn + ni * 8 + tg * 2;
                float b0 = bias[bn + c], b1 = bias[bn + c + 1];
                tile[r][c]         = acc[mi][ni][0] + b0;
                tile[r][c + 1]     = acc[mi][ni][1] + b1;
                tile[r + 8][c]     = acc[mi][ni][2] + b0;
                tile[r + 8][c + 1] = acc[mi][ni][3] + b1;
            }
        }
        __syncthreads();

        // 8 warps x 32 units: unit = (row, group); 64 values = 2 per lane
        for (int u = 0; u < 32; u++) {
            int unit = warp * 32 + u;      // 0..255
            int r  = unit >> 1;
            int gr = unit & 1;
            float v0 = tile[r][gr * 64 + lane];
            float v1 = tile[r][gr * 64 + 32 + lane];
            float m = fmaxf(v0, v1);
            #pragma unroll
            for (int o = 16; o; o >>= 1) m = fmaxf(m, __shfl_xor_sync(0xffffffffu, m, o));
            float e0 = __expf(v0 - m), e1 = __expf(v1 - m);
            float s = e0 + e1;
            #pragma unroll
            for (int o = 16; o; o >>= 1) s += __shfl_xor_sync(0xffffffffu, s, o);
            float inv = 1.f / s;
            size_t base = (size_t)(bm + r) * N + bn + gr * 64;
            C[base + lane]      = e0 * inv;
            C[base + 32 + lane] = e1 * inv;
        }
    }
}

// ---------------------------------------------------------------------------
// KV partials: KVp[chunk,bh,d,e] = sum_{s in chunk} K[b,s,h,d] * V[b,s,h,e]
// ---------------------------------------------------------------------------
__global__ void __launch_bounds__(256)
kv_partial(const float* __restrict__ Ksm, const float* __restrict__ V,
           float* __restrict__ KVp) {
    __shared__ float Ks[32][64];
    __shared__ float Vs[32][64];
    const int chunk = blockIdx.x;
    const int bh = blockIdx.y;
    const int b = bh >> 4, h = bh & 15;
    const int tid = threadIdx.x;
    const int td = (tid >> 4) * 4;
    const int te = (tid & 15) * 4;
    float acc[4][4] = {};

    const size_t rowbase = ((size_t)b * SEQ + chunk * 512) * DMODEL + h * 64;

    for (int sub = 0; sub < 16; sub++) {
        #pragma unroll
        for (int i = 0; i < 2; i++) {
            int f = tid + i * 256;
            int r = f >> 4;
            int c = (f & 15) * 4;
            size_t ga = rowbase + (size_t)(sub * 32 + r) * DMODEL + c;
            *(float4*)&Ks[r][c] = *(const float4*)&Ksm[ga];
            *(float4*)&Vs[r][c] = *(const float4*)&V[ga];
        }
        __syncthreads();
        #pragma unroll
        for (int s = 0; s < 32; s++) {
            float4 k4 = *(float4*)&Ks[s][td];
            float4 v4 = *(float4*)&Vs[s][te];
            float kk[4] = {k4.x, k4.y, k4.z, k4.w};
            float vv[4] = {v4.x, v4.y, v4.z, v4.w};
            #pragma unroll
            for (int i = 0; i < 4; i++)
                #pragma unroll
                for (int j = 0; j < 4; j++)
                    acc[i][j] += kk[i] * vv[j];
        }
        __syncthreads();
    }

    float* out = KVp + ((size_t)chunk * BH + bh) * (HDIM * HDIM);
    #pragma unroll
    for (int i = 0; i < 4; i++)
        #pragma unroll
        for (int j = 0; j < 4; j++)
            out[(td + i) * 64 + te + j] = acc[i][j];
}

__global__ void __launch_bounds__(256)
kv_reduce(const float* __restrict__ KVp, float* __restrict__ KV) {
    int idx = blockIdx.x * blockDim.x + threadIdx.x;
    if (idx >= BH * HDIM * HDIM) return;
    float s = 0.f;
    #pragma unroll
    for (int c = 0; c < 8; c++)
        s += KVp[(size_t)c * BH * HDIM * HDIM + idx];
    KV[idx] = s;
}

// ---------------------------------------------------------------------------
// Apply: AO[b,s,h,e] = sum_d Q[b,s,h,d] * KV[bh,d,e]
// ---------------------------------------------------------------------------
__global__ void __launch_bounds__(256)
apply_kv(const float* __restrict__ Qsm, const float* __restrict__ KV,
         float* __restrict__ AO) {
    __shared__ float KVs[64][64];
    const int chunk = blockIdx.x;
    const int bh = blockIdx.y;
    const int b = bh >> 4, h = bh & 15;
    const int tid = threadIdx.x, warp = tid >> 5, lane = tid & 31;

    const float* kvsrc = KV + (size_t)bh * (HDIM * HDIM);
    #pragma unroll
    for (int i = 0; i < 4; i++) {
        int f = tid + i * 256;
        *(float4*)(&KVs[0][0] + f * 4) = *(const float4*)(kvsrc + f * 4);
    }
    __syncthreads();

    for (int r = 0; r < 32; r++) {
        int s = chunk * 256 + warp * 32 + r;
        size_t base = ((size_t)b * SEQ + s) * DMODEL + h * 64;
        float q0 = Qsm[base + lane];
        float q1 = Qsm[base + lane + 32];
        float o0 = 0.f, o1 = 0.f;
        #pragma unroll
        for (int d = 0; d < 64; d++) {
            float qd = __shfl_sync(0xffffffffu, (d < 32 ? q0 : q1), d & 31);
            o0 += qd * KVs[d][lane];
            o1 += qd * KVs[d][lane + 32];
        }
        AO[base + lane]      = o0;
        AO[base + lane + 32] = o1;
    }
}

// ---------------------------------------------------------------------------
// Launch
// ---------------------------------------------------------------------------
extern "C" void kernel_launch(void* const* d_in, const int* in_sizes, int n_in,
                              void* d_out, int out_size) {
    const float* x  = (const float*)d_in[0];
    const float* Wq = (const float*)d_in[1];
    const float* bq = (const float*)d_in[2];
    const float* Wk = (const float*)d_in[3];
    const float* bk = (const float*)d_in[4];
    const float* Wv = (const float*)d_in[5];
    const float* bv = (const float*)d_in[6];
    const float* Wo = (const float*)d_in[7];
    const float* bo = (const float*)d_in[8];
    float* out = (float*)d_out;

    float *Q, *K, *V, *AO, *KVp, *KV;
    cudaGetSymbolAddress((void**)&Q,   g_Q);
    cudaGetSymbolAddress((void**)&K,   g_K);
    cudaGetSymbolAddress((void**)&V,   g_V);
    cudaGetSymbolAddress((void**)&AO,  g_AO);
    cudaGetSymbolAddress((void**)&KVp, g_KVp);
    cudaGetSymbolAddress((void**)&KV,  g_KV);

    const int smem_bytes = (int)sizeof(SmemPipe);   // 107,520 B
    static bool attr_set = false;
    if (!attr_set) {
        cudaFuncSetAttribute(gemm_tf32<true>,  cudaFuncAttributeMaxDynamicSharedMemorySize, smem_bytes);
        cudaFuncSetAttribute(gemm_tf32<false>, cudaFuncAttributeMaxDynamicSharedMemorySize, smem_bytes);
        attr_set = true;
    }

    dim3 ggrid(DMODEL / BN, MROWS / BM);   // (8, 128)

    gemm_tf32<true ><<<ggrid, 256, smem_bytes>>>(x, Wq, bq, Q, MROWS, DMODEL, DMODEL);
    gemm_tf32<true ><<<ggrid, 256, smem_bytes>>>(x, Wk, bk, K, MROWS, DMODEL, DMODEL);
    gemm_tf32<false><<<ggrid, 256, smem_bytes>>>(x, Wv, bv, V, MROWS, DMODEL, DMODEL);

    kv_partial<<<dim3(8, BH), 256>>>(K, V, KVp);
    kv_reduce<<<(BH * HDIM * HDIM + 255) / 256, 256>>>(KVp, KV);
    apply_kv<<<dim3(16, BH), 256>>>(Q, KV, AO);

    gemm_tf32<false><<<ggrid, 256, smem_bytes>>>(AO, Wo, bo, out, MROWS, DMODEL, DMODEL);
}

// round 3
// speedup vs baseline: 1.2008x; 1.0593x over previous
#include <cuda_runtime.h>
#include <cuda_bf16.h>
#include <cstdint>

// Problem constants
#define BATCH 4
#define SEQ 4096
#define DMODEL 1024
#define NHEAD 16
#define HDIM 64
#define MROWS (BATCH * SEQ)        // 16384
#define BH (BATCH * NHEAD)         // 64
#define KV_CHUNKS 32

// Scratch (device globals; no cudaMalloc allowed)
__device__ float g_X[MROWS * DMODEL];            // tf32-rounded x
__device__ float g_W[4][DMODEL * DMODEL];        // tf32-rounded Wq,Wk,Wv,Wo
__device__ float g_Q[MROWS * DMODEL];
__device__ float g_K[MROWS * DMODEL];
__device__ float g_V[MROWS * DMODEL];
__device__ float g_AO[MROWS * DMODEL];
__device__ float g_KVp[KV_CHUNKS * BH * HDIM * HDIM];
__device__ float g_KV[BH * HDIM * HDIM];

// ---------------------------------------------------------------------------
// Helpers
// ---------------------------------------------------------------------------
__device__ __forceinline__ float tf32r(float x) {
    uint32_t u;
    asm("cvt.rna.tf32.f32 %0, %1;" : "=r"(u) : "f"(x));
    return __uint_as_float(u);
}

__device__ __forceinline__ void mma_tf32(float c[4], const uint32_t a[4], const uint32_t b[2]) {
    asm volatile(
        "mma.sync.aligned.m16n8k8.row.col.f32.tf32.tf32.f32 "
        "{%0,%1,%2,%3}, {%4,%5,%6,%7}, {%8,%9}, {%0,%1,%2,%3};\n"
        : "+f"(c[0]), "+f"(c[1]), "+f"(c[2]), "+f"(c[3])
        : "r"(a[0]), "r"(a[1]), "r"(a[2]), "r"(a[3]), "r"(b[0]), "r"(b[1]));
}

__device__ __forceinline__ void cp_async16(void* smem, const void* gmem) {
    uint32_t s = (uint32_t)__cvta_generic_to_shared(smem);
    asm volatile("cp.async.cg.shared.global [%0], [%1], 16;\n" :: "r"(s), "l"(gmem));
}
__device__ __forceinline__ void cp_commit() { asm volatile("cp.async.commit_group;\n"); }
template<int N>
__device__ __forceinline__ void cp_wait() { asm volatile("cp.async.wait_group %0;\n" :: "n"(N)); }

// ---------------------------------------------------------------------------
// Pre-round: y = tf32_round(x), float4 vectorized
// ---------------------------------------------------------------------------
__global__ void __launch_bounds__(256)
round_tf32(const float* __restrict__ in, float* __restrict__ out, int n4) {
    int i = blockIdx.x * blockDim.x + threadIdx.x;
    if (i >= n4) return;
    float4 v = ((const float4*)in)[i];
    v.x = tf32r(v.x); v.y = tf32r(v.y); v.z = tf32r(v.z); v.w = tf32r(v.w);
    ((float4*)out)[i] = v;
}

// ---------------------------------------------------------------------------
// Pipelined TF32 GEMM: C[M,N] = A[M,K] @ B[K,N] + bias[N], optional fused
// per-64-col-group softmax. Inputs must already be tf32-rounded.
// BM=128 BN=128 BK=32, 3-stage cp.async, 128 threads, warp tile 64x64.
// ---------------------------------------------------------------------------
#define BM 128
#define BN 128
#define BK 32
#define STAGES 3
#define AS_STRIDE (BK + 4)     // 36
#define BS_STRIDE (BN + 8)     // 136
#define TILE_STRIDE (BN + 4)   // 132

struct SmemPipe {
    float As[STAGES][BM][AS_STRIDE];
    float Bs[STAGES][BK][BS_STRIDE];
};

template<bool DO_SOFTMAX>
__global__ void __launch_bounds__(128, 2)
gemm_tf32(const float* __restrict__ A, const float* __restrict__ B,
          const float* __restrict__ bias, float* __restrict__ C,
          int M, int N, int K) {
    extern __shared__ char smem_raw[];
    SmemPipe& sp = *reinterpret_cast<SmemPipe*>(smem_raw);
    float (*tile)[TILE_STRIDE] = reinterpret_cast<float(*)[TILE_STRIDE]>(smem_raw);

    const int tid  = threadIdx.x;
    const int warp = tid >> 5;
    const int lane = tid & 31;
    const int g  = lane >> 2;
    const int tg = lane & 3;
    const int wm = (warp >> 1) * 64;   // 0 / 64
    const int wn = (warp & 1) * 64;    // 0 / 64
    const int bm = blockIdx.y * BM;
    const int bn = blockIdx.x * BN;

    const int T = K / BK;   // 32

    auto load_stage = [&](int kt, int st) {
        #pragma unroll
        for (int i = 0; i < 8; i++) {
            int f = tid + i * 128;
            int r = f >> 3, c = (f & 7) * 4;
            cp_async16(&sp.As[st][r][c], &A[(size_t)(bm + r) * K + kt + c]);
        }
        #pragma unroll
        for (int i = 0; i < 8; i++) {
            int f = tid + i * 128;
            int r = f >> 5, c = (f & 31) * 4;
            cp_async16(&sp.Bs[st][r][c], &B[(size_t)(kt + r) * N + bn + c]);
        }
        cp_commit();
    };

    float acc[4][8][4] = {};

    load_stage(0, 0);
    load_stage(BK, 1);

    for (int t = 0; t < T; t++) {
        if (t > 0) __syncthreads();
        if (t + 2 < T) {
            load_stage((t + 2) * BK, (t + 2) % STAGES);
            cp_wait<2>();
        } else if (t + 1 < T) {
            cp_wait<1>();
        } else {
            cp_wait<0>();
        }
        __syncthreads();

        const int st = t % STAGES;
        #pragma unroll
        for (int k0 = 0; k0 < BK; k0 += 8) {
            uint32_t af[4][4];
            uint32_t bf[8][2];
            #pragma unroll
            for (int mi = 0; mi < 4; mi++) {
                int m0 = wm + mi * 16;
                af[mi][0] = __float_as_uint(sp.As[st][m0 + g    ][k0 + tg    ]);
                af[mi][1] = __float_as_uint(sp.As[st][m0 + g + 8][k0 + tg    ]);
                af[mi][2] = __float_as_uint(sp.As[st][m0 + g    ][k0 + tg + 4]);
                af[mi][3] = __float_as_uint(sp.As[st][m0 + g + 8][k0 + tg + 4]);
            }
            #pragma unroll
            for (int ni = 0; ni < 8; ni++) {
                int n0 = wn + ni * 8;
                bf[ni][0] = __float_as_uint(sp.Bs[st][k0 + tg    ][n0 + g]);
                bf[ni][1] = __float_as_uint(sp.Bs[st][k0 + tg + 4][n0 + g]);
            }
            #pragma unroll
            for (int mi = 0; mi < 4; mi++)
                #pragma unroll
                for (int ni = 0; ni < 8; ni++)
                    mma_tf32(acc[mi][ni], af[mi], bf[ni]);
        }
    }

    if (!DO_SOFTMAX) {
        #pragma unroll
        for (int mi = 0; mi < 4; mi++) {
            int row = bm + wm + mi * 16 + g;
            #pragma unroll
            for (int ni = 0; ni < 8; ni++) {
                int col = bn + wn + ni * 8 + tg * 2;
                float b0 = bias[col], b1 = bias[col + 1];
                C[(size_t)row * N + col]           = acc[mi][ni][0] + b0;
                C[(size_t)row * N + col + 1]       = acc[mi][ni][1] + b1;
                C[(size_t)(row + 8) * N + col]     = acc[mi][ni][2] + b0;
                C[(size_t)(row + 8) * N + col + 1] = acc[mi][ni][3] + b1;
            }
        }
    } else {
        __syncthreads();
        #pragma unroll
        for (int mi = 0; mi < 4; mi++) {
            int r = wm + mi * 16 + g;
            #pragma unroll
            for (int ni = 0; ni < 8; ni++) {
                int c = wn + ni * 8 + tg * 2;
                float b0 = bias[bn + c], b1 = bias[bn + c + 1];
                tile[r][c]         = acc[mi][ni][0] + b0;
                tile[r][c + 1]     = acc[mi][ni][1] + b1;
                tile[r + 8][c]     = acc[mi][ni][2] + b0;
                tile[r + 8][c + 1] = acc[mi][ni][3] + b1;
            }
        }
        __syncthreads();

        // 4 warps x 64 units: unit = (row, 64-col group)
        for (int u = 0; u < 64; u++) {
            int unit = warp * 64 + u;      // 0..255
            int r  = unit >> 1;
            int gr = unit & 1;
            float v0 = tile[r][gr * 64 + lane];
            float v1 = tile[r][gr * 64 + 32 + lane];
            float m = fmaxf(v0, v1);
            #pragma unroll
            for (int o = 16; o; o >>= 1) m = fmaxf(m, __shfl_xor_sync(0xffffffffu, m, o));
            float e0 = __expf(v0 - m), e1 = __expf(v1 - m);
            float s = e0 + e1;
            #pragma unroll
            for (int o = 16; o; o >>= 1) s += __shfl_xor_sync(0xffffffffu, s, o);
            float inv = 1.f / s;
            size_t base = (size_t)(bm + r) * N + bn + gr * 64;
            C[base + lane]      = e0 * inv;
            C[base + 32 + lane] = e1 * inv;
        }
    }
}

// ---------------------------------------------------------------------------
// KV partials: KVp[chunk,bh,d,e] = sum_{s in chunk} K[b,s,h,d] * V[b,s,h,e]
// grid (KV_CHUNKS, 64), chunk = 128 rows
// ---------------------------------------------------------------------------
__global__ void __launch_bounds__(256)
kv_partial(const float* __restrict__ Ksm, const float* __restrict__ V,
           float* __restrict__ KVp) {
    __shared__ float Ks[32][64];
    __shared__ float Vs[32][64];
    const int chunk = blockIdx.x;
    const int bh = blockIdx.y;
    const int b = bh >> 4, h = bh & 15;
    const int tid = threadIdx.x;
    const int td = (tid >> 4) * 4;
    const int te = (tid & 15) * 4;
    float acc[4][4] = {};

    const int rows_per_chunk = SEQ / KV_CHUNKS;   // 128
    const size_t rowbase = ((size_t)b * SEQ + chunk * rows_per_chunk) * DMODEL + h * 64;

    for (int sub = 0; sub < rows_per_chunk / 32; sub++) {
        #pragma unroll
        for (int i = 0; i < 2; i++) {
            int f = tid + i * 256;
            int r = f >> 4;
            int c = (f & 15) * 4;
            size_t ga = rowbase + (size_t)(sub * 32 + r) * DMODEL + c;
            *(float4*)&Ks[r][c] = *(const float4*)&Ksm[ga];
            *(float4*)&Vs[r][c] = *(const float4*)&V[ga];
        }
        __syncthreads();
        #pragma unroll
        for (int s = 0; s < 32; s++) {
            float4 k4 = *(float4*)&Ks[s][td];
            float4 v4 = *(float4*)&Vs[s][te];
            float kk[4] = {k4.x, k4.y, k4.z, k4.w};
            float vv[4] = {v4.x, v4.y, v4.z, v4.w};
            #pragma unroll
            for (int i = 0; i < 4; i++)
                #pragma unroll
                for (int j = 0; j < 4; j++)
                    acc[i][j] += kk[i] * vv[j];
        }
        __syncthreads();
    }

    float* out = KVp + ((size_t)chunk * BH + bh) * (HDIM * HDIM);
    #pragma unroll
    for (int i = 0; i < 4; i++)
        #pragma unroll
        for (int j = 0; j < 4; j++)
            out[(td + i) * 64 + te + j] = acc[i][j];
}

__global__ void __launch_bounds__(256)
kv_reduce(const float* __restrict__ KVp, float* __restrict__ KV) {
    int idx = blockIdx.x * blockDim.x + threadIdx.x;
    if (idx >= BH * HDIM * HDIM) return;
    float s = 0.f;
    #pragma unroll
    for (int c = 0; c < KV_CHUNKS; c++)
        s += KVp[(size_t)c * BH * HDIM * HDIM + idx];
    KV[idx] = s;
}

// ---------------------------------------------------------------------------
// Apply: AO[b,s,h,e] = tf32_round( sum_d Q[b,s,h,d] * KV[bh,d,e] )
// ---------------------------------------------------------------------------
__global__ void __launch_bounds__(256)
apply_kv(const float* __restrict__ Qsm, const float* __restrict__ KV,
         float* __restrict__ AO) {
    __shared__ float KVs[64][64];
    const int chunk = blockIdx.x;
    const int bh = blockIdx.y;
    const int b = bh >> 4, h = bh & 15;
    const int tid = threadIdx.x, warp = tid >> 5, lane = tid & 31;

    const float* kvsrc = KV + (size_t)bh * (HDIM * HDIM);
    #pragma unroll
    for (int i = 0; i < 4; i++) {
        int f = tid + i * 256;
        *(float4*)(&KVs[0][0] + f * 4) = *(const float4*)(kvsrc + f * 4);
    }
    __syncthreads();

    for (int r = 0; r < 32; r++) {
        int s = chunk * 256 + warp * 32 + r;
        size_t base = ((size_t)b * SEQ + s) * DMODEL + h * 64;
        float q0 = Qsm[base + lane];
        float q1 = Qsm[base + lane + 32];
        float o0 = 0.f, o1 = 0.f;
        #pragma unroll
        for (int d = 0; d < 64; d++) {
            float qd = __shfl_sync(0xffffffffu, (d < 32 ? q0 : q1), d & 31);
            o0 += qd * KVs[d][lane];
            o1 += qd * KVs[d][lane + 32];
        }
        AO[base + lane]      = tf32r(o0);
        AO[base + 32 + lane] = tf32r(o1);
    }
}

// ---------------------------------------------------------------------------
// Launch
// ---------------------------------------------------------------------------
extern "C" void kernel_launch(void* const* d_in, const int* in_sizes, int n_in,
                              void* d_out, int out_size) {
    const float* x  = (const float*)d_in[0];
    const float* Wq = (const float*)d_in[1];
    const float* bq = (const float*)d_in[2];
    const float* Wk = (const float*)d_in[3];
    const float* bk = (const float*)d_in[4];
    const float* Wv = (const float*)d_in[5];
    const float* bv = (const float*)d_in[6];
    const float* Wo = (const float*)d_in[7];
    const float* bo = (const float*)d_in[8];
    float* out = (float*)d_out;

    float *X, *W, *Q, *K, *V, *AO, *KVp, *KV;
    cudaGetSymbolAddress((void**)&X,   g_X);
    cudaGetSymbolAddress((void**)&W,   g_W);
    cudaGetSymbolAddress((void**)&Q,   g_Q);
    cudaGetSymbolAddress((void**)&K,   g_K);
    cudaGetSymbolAddress((void**)&V,   g_V);
    cudaGetSymbolAddress((void**)&AO,  g_AO);
    cudaGetSymbolAddress((void**)&KVp, g_KVp);
    cudaGetSymbolAddress((void**)&KV,  g_KV);

    float* Wqr = W;
    float* Wkr = W + (size_t)DMODEL * DMODEL;
    float* Wvr = W + 2 * (size_t)DMODEL * DMODEL;
    float* Wor = W + 3 * (size_t)DMODEL * DMODEL;

    const int smem_bytes = (int)sizeof(SmemPipe);   // 107,520 B
    static bool attr_set = false;
    if (!attr_set) {
        cudaFuncSetAttribute(gemm_tf32<true>,  cudaFuncAttributeMaxDynamicSharedMemorySize, smem_bytes);
        cudaFuncSetAttribute(gemm_tf32<false>, cudaFuncAttributeMaxDynamicSharedMemorySize, smem_bytes);
        attr_set = true;
    }

    // pre-round inputs to tf32
    const int n4x = MROWS * DMODEL / 4;
    const int n4w = DMODEL * DMODEL / 4;
    round_tf32<<<(n4x + 255) / 256, 256>>>(x,  X,   n4x);
    round_tf32<<<(n4w + 255) / 256, 256>>>(Wq, Wqr, n4w);
    round_tf32<<<(n4w + 255) / 256, 256>>>(Wk, Wkr, n4w);
    round_tf32<<<(n4w + 255) / 256, 256>>>(Wv, Wvr, n4w);
    round_tf32<<<(n4w + 255) / 256, 256>>>(Wo, Wor, n4w);

    dim3 ggrid(DMODEL / BN, MROWS / BM);   // (8, 128)

    gemm_tf32<true ><<<ggrid, 128, smem_bytes>>>(X, Wqr, bq, Q, MROWS, DMODEL, DMODEL);
    gemm_tf32<true ><<<ggrid, 128, smem_bytes>>>(X, Wkr, bk, K, MROWS, DMODEL, DMODEL);
    gemm_tf32<false><<<ggrid, 128, smem_bytes>>>(X, Wvr, bv, V, MROWS, DMODEL, DMODEL);

    kv_partial<<<dim3(KV_CHUNKS, BH), 256>>>(K, V, KVp);
    kv_reduce<<<(BH * HDIM * HDIM + 255) / 256, 256>>>(KVp, KV);
    apply_kv<<<dim3(16, BH), 256>>>(Q, KV, AO);

    gemm_tf32<false><<<ggrid, 128, smem_bytes>>>(AO, Wor, bo, out, MROWS, DMODEL, DMODEL);
}